// round 4
// baseline (speedup 1.0000x reference)
#include <cuda_runtime.h>
#include <cuda_bf16.h>
#include <cstdint>

// ---------------- problem constants ----------------
#define BATCH   16
#define DMODEL  256
#define KCODES  512
#define HP      128
#define WP      128
#define NROWS   (BATCH*HP*WP)                         // 262144
#define QUANT_ELEMS ((long long)BATCH*DMODEL*HP*WP)   // 67108864
#define IDX_ELEMS   (BATCH*HP*WP)
#define BN_EPS 1e-5f
#define MARGIN 4.0f

// ---------------- scratch ----------------
__device__ float          g_fmap[(long long)NROWS * DMODEL];   // fp32 fmap
__device__ __nv_bfloat16  g_fmapb[(long long)NROWS * DMODEL];  // bf16 fmap
__device__ __nv_bfloat16  g_cbkb[KCODES * DMODEL];             // bf16 codebook
__device__ float g_c2[KCODES];
__device__ float g_conv_partial[2048];
__device__ float g_vq_partial[2048];

// ---------------- f32x2 helpers (conv kernel) ----------------
__device__ __forceinline__ unsigned long long pack2(float a, float b) {
    unsigned long long r;
    asm("mov.b64 %0, {%1, %2};" : "=l"(r) : "f"(a), "f"(b));
    return r;
}
__device__ __forceinline__ void unpack2(unsigned long long v, float& a, float& b) {
    asm("mov.b64 {%0, %1}, %2;" : "=f"(a), "=f"(b) : "l"(v));
}
__device__ __forceinline__ void fma2(unsigned long long& acc,
                                     unsigned long long a, unsigned long long b) {
    asm("fma.rn.f32x2 %0, %1, %2, %3;" : "=l"(acc) : "l"(a), "l"(b), "l"(acc));
}

// ---------------- smem address / cp.async / ldmatrix / mma ----------------
__device__ __forceinline__ uint32_t smem_u32(const void* p) {
    uint32_t a;
    asm("{ .reg .u64 t; cvta.to.shared.u64 t, %1; cvt.u32.u64 %0, t; }" : "=r"(a) : "l"(p));
    return a;
}
__device__ __forceinline__ void cp_async16(uint32_t dst, const void* src) {
    asm volatile("cp.async.cg.shared.global [%0], [%1], 16;" :: "r"(dst), "l"(src) : "memory");
}
#define CP_COMMIT() asm volatile("cp.async.commit_group;" ::: "memory")
#define CP_WAIT(n)  asm volatile("cp.async.wait_group %0;" :: "n"(n) : "memory")

__device__ __forceinline__ void ldm_x4(uint32_t addr, uint32_t& r0, uint32_t& r1,
                                       uint32_t& r2, uint32_t& r3) {
    asm volatile("ldmatrix.sync.aligned.m8n8.x4.shared.b16 {%0,%1,%2,%3}, [%4];"
                 : "=r"(r0), "=r"(r1), "=r"(r2), "=r"(r3) : "r"(addr));
}
__device__ __forceinline__ void mma16816(float* c, const uint32_t* a,
                                         uint32_t b0, uint32_t b1) {
    asm volatile("mma.sync.aligned.m16n8k16.row.col.f32.bf16.bf16.f32 "
                 "{%0,%1,%2,%3}, {%4,%5,%6,%7}, {%8,%9}, {%0,%1,%2,%3};"
                 : "+f"(c[0]), "+f"(c[1]), "+f"(c[2]), "+f"(c[3])
                 : "r"(a[0]), "r"(a[1]), "r"(a[2]), "r"(a[3]), "r"(b0), "r"(b1));
}

// =====================================================================
// Kernel 1: fused conv3x3(3->256)+bias+maxpool2x2+BN+exact GELU
//           writes fp32 fmap + bf16 fmap + per-block sum x^2
// =====================================================================
__global__ __launch_bounds__(256) void conv_kernel(
    const float* __restrict__ x, const float* __restrict__ cw,
    const float* __restrict__ cbias,
    const float* __restrict__ gam, const float* __restrict__ bet,
    const float* __restrict__ mu,  const float* __restrict__ var)
{
    const int bx = blockIdx.x;
    const int b  = bx >> 7;
    const int ph = bx & 127;
    const int d  = threadIdx.x;

    __shared__ __align__(16) float sIn[3][4][258];
    __shared__ float red[256];

    const int h0 = 2 * ph - 1;
    for (int t = threadIdx.x; t < 3 * 4 * 258; t += 256) {
        int c   = t / 1032;
        int rem = t - c * 1032;
        int i   = rem / 258;
        int j   = rem - i * 258;
        int gr  = h0 + i;
        int gc  = j - 1;
        float v = 0.f;
        if ((unsigned)gr < 256u && (unsigned)gc < 256u)
            v = x[(((b * 3 + c) << 8) + gr) * 256 + gc];
        sIn[c][i][j] = v;
    }

    unsigned long long w2[27];
#pragma unroll
    for (int j = 0; j < 27; j++) { float wv = cw[d * 27 + j]; w2[j] = pack2(wv, wv); }
    const float bias = cbias[d];
    const float inv  = gam[d] * rsqrtf(var[d] + BN_EPS);
    const float shf  = bet[d] - mu[d] * inv;

    __syncthreads();

    float sumsq = 0.f;
    const long long rowOut = (long long)bx * 128;

    for (int pw = 0; pw < 128; ++pw) {
        unsigned long long acc0 = 0ull, acc1 = 0ull;
#pragma unroll
        for (int c = 0; c < 3; c++) {
            const int wb = c * 9;
#pragma unroll
            for (int ro = 0; ro < 4; ro++) {
                const float* p = &sIn[c][ro][2 * pw];
                unsigned long long g01 = *reinterpret_cast<const unsigned long long*>(p);
                unsigned long long g23 = *reinterpret_cast<const unsigned long long*>(p + 2);
                float f0, f1, f2, f3;
                unpack2(g01, f0, f1);
                unpack2(g23, f2, f3);
                unsigned long long g12 = pack2(f1, f2);
                if (ro <= 2) {
                    fma2(acc0, g01, w2[wb + ro * 3 + 0]);
                    fma2(acc0, g12, w2[wb + ro * 3 + 1]);
                    fma2(acc0, g23, w2[wb + ro * 3 + 2]);
                }
                if (ro >= 1) {
                    fma2(acc1, g01, w2[wb + (ro - 1) * 3 + 0]);
                    fma2(acc1, g12, w2[wb + (ro - 1) * 3 + 1]);
                    fma2(acc1, g23, w2[wb + (ro - 1) * 3 + 2]);
                }
            }
        }
        float a0, a1, b0, b1;
        unpack2(acc0, a0, a1);
        unpack2(acc1, b0, b1);
        float m = fmaxf(fmaxf(a0, a1), fmaxf(b0, b1)) + bias;
        float v = m * inv + shf;
        float g = 0.5f * v * (1.0f + erff(v * 0.7071067811865476f));
        g_fmap [(rowOut + pw) * DMODEL + d] = g;
        g_fmapb[(rowOut + pw) * DMODEL + d] = __float2bfloat16(g);
        sumsq += g * g;
    }

    red[threadIdx.x] = sumsq;
    __syncthreads();
    for (int s = 128; s > 0; s >>= 1) {
        if (threadIdx.x < s) red[threadIdx.x] += red[threadIdx.x + s];
        __syncthreads();
    }
    if (threadIdx.x == 0) g_conv_partial[bx] = red[0];
}

// =====================================================================
// Kernel 2: codebook -> bf16 + exact fp32 squared norms. grid 512, block 256.
// =====================================================================
__global__ __launch_bounds__(256) void prep_cbk_kernel(const float* __restrict__ cbk)
{
    __shared__ float red[256];
    const int k = blockIdx.x;
    const int t = threadIdx.x;
    float v = cbk[k * DMODEL + t];
    g_cbkb[k * DMODEL + t] = __float2bfloat16(v);
    red[t] = v * v;
    __syncthreads();
    for (int s = 128; s > 0; s >>= 1) {
        if (t < s) red[t] += red[t + s];
        __syncthreads();
    }
    if (t == 0) g_c2[k] = red[0];
}

// =====================================================================
// Kernel 3: VQ via bf16 mma.sync + margin-filtered exact fp32 rescore,
//           fused with gather (quant NCHW write + indices + loss partial)
// grid 2048 (128 rows/CTA); 256 threads = 8 warps (4m x 2n)
// N in 2 halves of 256 codes; K in 4 chunks of 64; cp.async double-buffered
// =====================================================================
#define ASTRIDE 144
#define ATILE (128*ASTRIDE)        // 18432
#define BTILE (256*ASTRIDE)        // 36864
#define BUFBYTES (ATILE+BTILE)     // 55296
#define VQ_SMEM (2*BUFBYTES)       // 110592

__global__ __launch_bounds__(256, 1) void vq_kernel(const float* __restrict__ cbk,
                                                    float* __restrict__ out)
{
    extern __shared__ __align__(16) char dsm[];
    __shared__ float sc2[KCODES];
    __shared__ float sE[2][128];
    __shared__ int   sC[2][128];
    __shared__ int   s_idx[128];
    __shared__ float s_red[128];

    const int tid  = threadIdx.x;
    const int wid  = tid >> 5;
    const int lane = tid & 31;
    const int wm   = wid >> 1;      // 0..3  (m block of 32 rows)
    const int wn   = wid & 1;       // 0..1  (n block of 128 codes within half)
    const int rowBase = blockIdx.x * 128;

    sc2[tid]       = g_c2[tid];
    sc2[tid + 256] = g_c2[tid + 256];

    const uint32_t smBase = smem_u32(dsm);

    auto issue_phase = [&](int p, int bufsel) {
        const int half = p >> 2;
        const int kc   = p & 3;
        const uint32_t buf = smBase + bufsel * BUFBYTES;
#pragma unroll
        for (int it = 0; it < 4; it++) {
            int idx = tid + it * 256;
            int r   = idx >> 3;
            int g   = idx & 7;
            const void* src = g_fmapb + ((long long)(rowBase + r) * DMODEL + kc * 64 + g * 8);
            cp_async16(buf + r * ASTRIDE + g * 16, src);
        }
#pragma unroll
        for (int it = 0; it < 8; it++) {
            int idx = tid + it * 256;
            int c   = idx >> 3;
            int g   = idx & 7;
            const void* src = g_cbkb + ((half * 256 + c) * DMODEL + kc * 64 + g * 8);
            cp_async16(buf + ATILE + c * ASTRIDE + g * 16, src);
        }
        CP_COMMIT();
    };

    float bestE[4];
    int   bestC[4];
#pragma unroll
    for (int s = 0; s < 4; s++) { bestE[s] = __int_as_float(0x7f800000); bestC[s] = 0; }

    float acc[2][16][4];

    issue_phase(0, 0);
    __syncthreads();

    for (int p = 0; p < 8; p++) {
        const int half = p >> 2;
        const int kc   = p & 3;
        const uint32_t buf = smBase + (p & 1) * BUFBYTES;

        if (p < 7) { issue_phase(p + 1, (p + 1) & 1); CP_WAIT(1); }
        else       { CP_WAIT(0); }
        __syncthreads();

        if (kc == 0) {
#pragma unroll
            for (int mt = 0; mt < 2; mt++)
#pragma unroll
                for (int j = 0; j < 16; j++)
#pragma unroll
                    for (int q = 0; q < 4; q++) acc[mt][j][q] = 0.f;
        }

#pragma unroll
        for (int ks = 0; ks < 4; ks++) {
            uint32_t a[2][4];
#pragma unroll
            for (int mt = 0; mt < 2; mt++) {
                int grp = lane >> 3, rim = lane & 7;
                uint32_t row  = wm * 32 + mt * 16 + (grp & 1) * 8 + rim;
                uint32_t koff = ks * 32 + (grp >> 1) * 16;
                ldm_x4(buf + row * ASTRIDE + koff, a[mt][0], a[mt][1], a[mt][2], a[mt][3]);
            }
#pragma unroll
            for (int jj = 0; jj < 8; jj++) {
                int grp = lane >> 3, rim = lane & 7;
                uint32_t codeInTile = wn * 128 + (2 * jj + (grp >> 1)) * 8 + rim;
                uint32_t addr = buf + ATILE + codeInTile * ASTRIDE + ks * 32 + (grp & 1) * 16;
                uint32_t b0, b1, b2, b3;
                ldm_x4(addr, b0, b1, b2, b3);
#pragma unroll
                for (int mt = 0; mt < 2; mt++) {
                    mma16816(acc[mt][2 * jj],     a[mt], b0, b1);
                    mma16816(acc[mt][2 * jj + 1], a[mt], b2, b3);
                }
            }
        }
        __syncthreads();

        if (kc == 3) {
            // per-half epilogue: approx distances + exact fp32 rescore of candidates
#pragma unroll
            for (int slot = 0; slot < 4; slot++) {
                const int mt = slot >> 1;
                const int rh = slot & 1;
                const int row = rowBase + wm * 32 + mt * 16 + rh * 8 + (lane >> 2);

                float mn = __int_as_float(0x7f800000);
#pragma unroll
                for (int j = 0; j < 16; j++) {
#pragma unroll
                    for (int q = 0; q < 2; q++) {
                        int code = half * 256 + wn * 128 + j * 8 + (lane & 3) * 2 + q;
                        float d = fmaf(-2.f, acc[mt][j][rh * 2 + q], sc2[code]);
                        acc[mt][j][rh * 2 + q] = d;
                        mn = fminf(mn, d);
                    }
                }
                mn = fminf(mn, __shfl_xor_sync(0xffffffffu, mn, 1));
                mn = fminf(mn, __shfl_xor_sync(0xffffffffu, mn, 2));
                const float thr = mn + MARGIN;

                const float4* xrow = reinterpret_cast<const float4*>(g_fmap + (long long)row * DMODEL);
#pragma unroll 1
                for (int j = 0; j < 16; j++) {
#pragma unroll 1
                    for (int q = 0; q < 2; q++) {
                        float d = acc[mt][j][rh * 2 + q];
                        if (d < thr) {
                            int code = half * 256 + wn * 128 + j * 8 + (lane & 3) * 2 + q;
                            const float4* crow = reinterpret_cast<const float4*>(cbk + (long long)code * DMODEL);
                            float s0 = 0.f, s1 = 0.f, s2 = 0.f, s3 = 0.f;
#pragma unroll 8
                            for (int u = 0; u < 64; u++) {
                                float4 av = xrow[u];
                                float4 bv = crow[u];
                                s0 = fmaf(av.x, bv.x, s0);
                                s1 = fmaf(av.y, bv.y, s1);
                                s2 = fmaf(av.z, bv.z, s2);
                                s3 = fmaf(av.w, bv.w, s3);
                            }
                            float de = fmaf(-2.f, (s0 + s1) + (s2 + s3), sc2[code]);
                            if (de < bestE[slot] || (de == bestE[slot] && code < bestC[slot])) {
                                bestE[slot] = de;
                                bestC[slot] = code;
                            }
                        }
                    }
                }
            }
        }
    }

    // ---- combine: quad lanes -> per-warp; then across the two wn warps ----
#pragma unroll
    for (int slot = 0; slot < 4; slot++) {
        const int mt = slot >> 1;
        const int rh = slot & 1;
        float e = bestE[slot];
        int   c = bestC[slot];
#pragma unroll
        for (int off = 1; off < 4; off <<= 1) {
            float oe = __shfl_xor_sync(0xffffffffu, e, off);
            int   oc = __shfl_xor_sync(0xffffffffu, c, off);
            if (oe < e || (oe == e && oc < c)) { e = oe; c = oc; }
        }
        if ((lane & 3) == 0) {
            const int r = wm * 32 + mt * 16 + rh * 8 + (lane >> 2);
            sE[wn][r] = e;
            sC[wn][r] = c;
        }
    }
    __syncthreads();

    if (tid < 128) {
        float e0 = sE[0][tid], e1 = sE[1][tid];
        int   c0 = sC[0][tid], c1 = sC[1][tid];
        bool take1 = (e1 < e0) || (e1 == e0 && c1 < c0);
        int   c = take1 ? c1 : c0;
        float e = take1 ? e1 : e0;
        s_idx[tid] = c;
        s_red[tid] = e;
        // indices output (as float)
        out[QUANT_ELEMS + (long long)blockIdx.x * 128 + tid] = (float)c;
    }
    __syncthreads();

    // loss partial
    for (int s = 64; s > 0; s >>= 1) {
        if (tid < s) s_red[tid] += s_red[tid + s];
        __syncthreads();
    }
    if (tid == 0) g_vq_partial[blockIdx.x] = s_red[0];

    // quant NCHW writes (this CTA == one (b,h) gather block; w = row index)
    {
        const int b = blockIdx.x >> 7;
        const int h = blockIdx.x & 127;
        const int w    = tid & 127;
        const int doff = tid >> 7;
        const int myIdx = s_idx[w];
        for (int db = 0; db < DMODEL; db += 2) {
            int d = db + doff;
            float qv = cbk[myIdx * DMODEL + d];
            out[(((long long)(b * DMODEL + d) * 128 + h) << 7) + w] = qv;
        }
    }
}

// =====================================================================
// Kernel 4: final loss = (sum x^2 + sum (c^2-2x.c)) / (B*N*D)
// =====================================================================
__global__ void loss_kernel(float* __restrict__ out)
{
    __shared__ float red[256];
    float s = 0.f;
    for (int i = threadIdx.x; i < 2048; i += 256)
        s += g_conv_partial[i] + g_vq_partial[i];
    red[threadIdx.x] = s;
    __syncthreads();
    for (int st = 128; st > 0; st >>= 1) {
        if (threadIdx.x < st) red[threadIdx.x] += red[threadIdx.x + st];
        __syncthreads();
    }
    if (threadIdx.x == 0)
        out[QUANT_ELEMS + IDX_ELEMS] = red[0] * (1.0f / 67108864.0f);
}

// =====================================================================
extern "C" void kernel_launch(void* const* d_in, const int* in_sizes, int n_in,
                              void* d_out, int out_size)
{
    (void)in_sizes; (void)n_in; (void)out_size;
    const float* x    = (const float*)d_in[0];
    const float* cw   = (const float*)d_in[1];
    const float* cbia = (const float*)d_in[2];
    const float* gam  = (const float*)d_in[3];
    const float* bet  = (const float*)d_in[4];
    const float* mu   = (const float*)d_in[5];
    const float* var  = (const float*)d_in[6];
    const float* cbk  = (const float*)d_in[7];
    float* out = (float*)d_out;

    cudaFuncSetAttribute(vq_kernel, cudaFuncAttributeMaxDynamicSharedMemorySize, VQ_SMEM);

    conv_kernel<<<2048, 256>>>(x, cw, cbia, gam, bet, mu, var);
    prep_cbk_kernel<<<512, 256>>>(cbk);
    vq_kernel<<<2048, 256, VQ_SMEM>>>(cbk, out);
    loss_kernel<<<1, 256>>>(out);
}

// round 5
// speedup vs baseline: 3.4859x; 3.4859x over previous
#include <cuda_runtime.h>
#include <cuda_bf16.h>
#include <cstdint>

// ---------------- problem constants ----------------
#define BATCH   16
#define DMODEL  256
#define KCODES  512
#define HP      128
#define WP      128
#define NROWS   (BATCH*HP*WP)                         // 262144
#define QUANT_ELEMS ((long long)BATCH*DMODEL*HP*WP)   // 67108864
#define IDX_ELEMS   (BATCH*HP*WP)
#define BN_EPS 1e-5f
#define MARGIN 4.0f

// ---------------- scratch ----------------
__device__ float          g_fmap[(long long)NROWS * DMODEL];   // fp32 fmap
__device__ __nv_bfloat16  g_fmapb[(long long)NROWS * DMODEL];  // bf16 fmap
__device__ __nv_bfloat16  g_cbkb[KCODES * DMODEL];             // bf16 codebook
__device__ float g_c2[KCODES];
__device__ float g_conv_partial[2048];
__device__ float g_vq_partial[2048];

// ---------------- f32x2 helpers (conv kernel) ----------------
__device__ __forceinline__ unsigned long long pack2(float a, float b) {
    unsigned long long r;
    asm("mov.b64 %0, {%1, %2};" : "=l"(r) : "f"(a), "f"(b));
    return r;
}
__device__ __forceinline__ void unpack2(unsigned long long v, float& a, float& b) {
    asm("mov.b64 {%0, %1}, %2;" : "=f"(a), "=f"(b) : "l"(v));
}
__device__ __forceinline__ void fma2(unsigned long long& acc,
                                     unsigned long long a, unsigned long long b) {
    asm("fma.rn.f32x2 %0, %1, %2, %3;" : "=l"(acc) : "l"(a), "l"(b), "l"(acc));
}

// ---------------- smem address / cp.async / ldmatrix / mma ----------------
__device__ __forceinline__ uint32_t smem_u32(const void* p) {
    uint32_t a;
    asm("{ .reg .u64 t; cvta.to.shared.u64 t, %1; cvt.u32.u64 %0, t; }" : "=r"(a) : "l"(p));
    return a;
}
__device__ __forceinline__ void cp_async16(uint32_t dst, const void* src) {
    asm volatile("cp.async.cg.shared.global [%0], [%1], 16;" :: "r"(dst), "l"(src) : "memory");
}
#define CP_COMMIT() asm volatile("cp.async.commit_group;" ::: "memory")
#define CP_WAIT(n)  asm volatile("cp.async.wait_group %0;" :: "n"(n) : "memory")

__device__ __forceinline__ void ldm_x4(uint32_t addr, uint32_t& r0, uint32_t& r1,
                                       uint32_t& r2, uint32_t& r3) {
    asm volatile("ldmatrix.sync.aligned.m8n8.x4.shared.b16 {%0,%1,%2,%3}, [%4];"
                 : "=r"(r0), "=r"(r1), "=r"(r2), "=r"(r3) : "r"(addr));
}
__device__ __forceinline__ void mma16816(float* c, const uint32_t* a,
                                         uint32_t b0, uint32_t b1) {
    asm volatile("mma.sync.aligned.m16n8k16.row.col.f32.bf16.bf16.f32 "
                 "{%0,%1,%2,%3}, {%4,%5,%6,%7}, {%8,%9}, {%0,%1,%2,%3};"
                 : "+f"(c[0]), "+f"(c[1]), "+f"(c[2]), "+f"(c[3])
                 : "r"(a[0]), "r"(a[1]), "r"(a[2]), "r"(a[3]), "r"(b0), "r"(b1));
}

// =====================================================================
// Kernel 1: fused conv3x3(3->256)+bias+maxpool2x2+BN+exact GELU
// =====================================================================
__global__ __launch_bounds__(256) void conv_kernel(
    const float* __restrict__ x, const float* __restrict__ cw,
    const float* __restrict__ cbias,
    const float* __restrict__ gam, const float* __restrict__ bet,
    const float* __restrict__ mu,  const float* __restrict__ var)
{
    const int bx = blockIdx.x;
    const int b  = bx >> 7;
    const int ph = bx & 127;
    const int d  = threadIdx.x;

    __shared__ __align__(16) float sIn[3][4][258];
    __shared__ float red[256];

    const int h0 = 2 * ph - 1;
    for (int t = threadIdx.x; t < 3 * 4 * 258; t += 256) {
        int c   = t / 1032;
        int rem = t - c * 1032;
        int i   = rem / 258;
        int j   = rem - i * 258;
        int gr  = h0 + i;
        int gc  = j - 1;
        float v = 0.f;
        if ((unsigned)gr < 256u && (unsigned)gc < 256u)
            v = x[(((b * 3 + c) << 8) + gr) * 256 + gc];
        sIn[c][i][j] = v;
    }

    unsigned long long w2[27];
#pragma unroll
    for (int j = 0; j < 27; j++) { float wv = cw[d * 27 + j]; w2[j] = pack2(wv, wv); }
    const float bias = cbias[d];
    const float inv  = gam[d] * rsqrtf(var[d] + BN_EPS);
    const float shf  = bet[d] - mu[d] * inv;

    __syncthreads();

    float sumsq = 0.f;
    const long long rowOut = (long long)bx * 128;

    for (int pw = 0; pw < 128; ++pw) {
        unsigned long long acc0 = 0ull, acc1 = 0ull;
#pragma unroll
        for (int c = 0; c < 3; c++) {
            const int wb = c * 9;
#pragma unroll
            for (int ro = 0; ro < 4; ro++) {
                const float* p = &sIn[c][ro][2 * pw];
                unsigned long long g01 = *reinterpret_cast<const unsigned long long*>(p);
                unsigned long long g23 = *reinterpret_cast<const unsigned long long*>(p + 2);
                float f0, f1, f2, f3;
                unpack2(g01, f0, f1);
                unpack2(g23, f2, f3);
                unsigned long long g12 = pack2(f1, f2);
                if (ro <= 2) {
                    fma2(acc0, g01, w2[wb + ro * 3 + 0]);
                    fma2(acc0, g12, w2[wb + ro * 3 + 1]);
                    fma2(acc0, g23, w2[wb + ro * 3 + 2]);
                }
                if (ro >= 1) {
                    fma2(acc1, g01, w2[wb + (ro - 1) * 3 + 0]);
                    fma2(acc1, g12, w2[wb + (ro - 1) * 3 + 1]);
                    fma2(acc1, g23, w2[wb + (ro - 1) * 3 + 2]);
                }
            }
        }
        float a0, a1, b0, b1;
        unpack2(acc0, a0, a1);
        unpack2(acc1, b0, b1);
        float m = fmaxf(fmaxf(a0, a1), fmaxf(b0, b1)) + bias;
        float v = m * inv + shf;
        float g = 0.5f * v * (1.0f + erff(v * 0.7071067811865476f));
        g_fmap [(rowOut + pw) * DMODEL + d] = g;
        g_fmapb[(rowOut + pw) * DMODEL + d] = __float2bfloat16(g);
        sumsq += g * g;
    }

    red[threadIdx.x] = sumsq;
    __syncthreads();
    for (int s = 128; s > 0; s >>= 1) {
        if (threadIdx.x < s) red[threadIdx.x] += red[threadIdx.x + s];
        __syncthreads();
    }
    if (threadIdx.x == 0) g_conv_partial[bx] = red[0];
}

// =====================================================================
// Kernel 2: codebook -> bf16 + exact fp32 squared norms
// =====================================================================
__global__ __launch_bounds__(256) void prep_cbk_kernel(const float* __restrict__ cbk)
{
    __shared__ float red[256];
    const int k = blockIdx.x;
    const int t = threadIdx.x;
    float v = cbk[k * DMODEL + t];
    g_cbkb[k * DMODEL + t] = __float2bfloat16(v);
    red[t] = v * v;
    __syncthreads();
    for (int s = 128; s > 0; s >>= 1) {
        if (t < s) red[t] += red[t + s];
        __syncthreads();
    }
    if (t == 0) g_c2[k] = red[0];
}

// =====================================================================
// Kernel 3: VQ via bf16 mma.sync + margin-filtered exact fp32 rescore,
//           fused gather (quant NCHW write + indices + loss partial)
// NOTE: acc[] must ONLY be touched from fully-unrolled loops (register file).
// =====================================================================
#define ASTRIDE 144
#define ATILE (128*ASTRIDE)        // 18432
#define BTILE (256*ASTRIDE)        // 36864
#define BUFBYTES (ATILE+BTILE)     // 55296
#define VQ_SMEM (2*BUFBYTES)       // 110592

__global__ __launch_bounds__(256, 1) void vq_kernel(const float* __restrict__ cbk,
                                                    float* __restrict__ out)
{
    extern __shared__ __align__(16) char dsm[];
    __shared__ float sc2[KCODES];
    __shared__ float sE[2][128];
    __shared__ int   sC[2][128];
    __shared__ int   s_idx[128];
    __shared__ float s_red[128];

    const int tid  = threadIdx.x;
    const int wid  = tid >> 5;
    const int lane = tid & 31;
    const int wm   = wid >> 1;
    const int wn   = wid & 1;
    const int rowBase = blockIdx.x * 128;

    sc2[tid]       = g_c2[tid];
    sc2[tid + 256] = g_c2[tid + 256];

    const uint32_t smBase = smem_u32(dsm);

    auto issue_phase = [&](int p, int bufsel) {
        const int half = p >> 2;
        const int kc   = p & 3;
        const uint32_t buf = smBase + bufsel * BUFBYTES;
#pragma unroll
        for (int it = 0; it < 4; it++) {
            int idx = tid + it * 256;
            int r   = idx >> 3;
            int g   = idx & 7;
            const void* src = g_fmapb + ((long long)(rowBase + r) * DMODEL + kc * 64 + g * 8);
            cp_async16(buf + r * ASTRIDE + g * 16, src);
        }
#pragma unroll
        for (int it = 0; it < 8; it++) {
            int idx = tid + it * 256;
            int c   = idx >> 3;
            int g   = idx & 7;
            const void* src = g_cbkb + ((half * 256 + c) * DMODEL + kc * 64 + g * 8);
            cp_async16(buf + ATILE + c * ASTRIDE + g * 16, src);
        }
        CP_COMMIT();
    };

    float bestE[4];
    int   bestC[4];
#pragma unroll
    for (int s = 0; s < 4; s++) { bestE[s] = __int_as_float(0x7f800000); bestC[s] = 0; }

    float acc[2][16][4];

    issue_phase(0, 0);
    __syncthreads();

    for (int p = 0; p < 8; p++) {
        const int half = p >> 2;
        const int kc   = p & 3;
        const uint32_t buf = smBase + (p & 1) * BUFBYTES;

        if (p < 7) { issue_phase(p + 1, (p + 1) & 1); CP_WAIT(1); }
        else       { CP_WAIT(0); }
        __syncthreads();

        if (kc == 0) {
#pragma unroll
            for (int mt = 0; mt < 2; mt++)
#pragma unroll
                for (int j = 0; j < 16; j++)
#pragma unroll
                    for (int q = 0; q < 4; q++) acc[mt][j][q] = 0.f;
        }

#pragma unroll
        for (int ks = 0; ks < 4; ks++) {
            uint32_t a[2][4];
#pragma unroll
            for (int mt = 0; mt < 2; mt++) {
                int grp = lane >> 3, rim = lane & 7;
                uint32_t row  = wm * 32 + mt * 16 + (grp & 1) * 8 + rim;
                uint32_t koff = ks * 32 + (grp >> 1) * 16;
                ldm_x4(buf + row * ASTRIDE + koff, a[mt][0], a[mt][1], a[mt][2], a[mt][3]);
            }
#pragma unroll
            for (int jj = 0; jj < 8; jj++) {
                int grp = lane >> 3, rim = lane & 7;
                uint32_t codeInTile = wn * 128 + (2 * jj + (grp >> 1)) * 8 + rim;
                uint32_t addr = buf + ATILE + codeInTile * ASTRIDE + ks * 32 + (grp & 1) * 16;
                uint32_t b0, b1, b2, b3;
                ldm_x4(addr, b0, b1, b2, b3);
#pragma unroll
                for (int mt = 0; mt < 2; mt++) {
                    mma16816(acc[mt][2 * jj],     a[mt], b0, b1);
                    mma16816(acc[mt][2 * jj + 1], a[mt], b2, b3);
                }
            }
        }
        __syncthreads();

        if (kc == 3) {
            // ---- epilogue: approx distances (registers only) + exact rescore ----
            const int cbase = half * 256 + wn * 128 + (lane & 3) * 2;
#pragma unroll
            for (int slot = 0; slot < 4; slot++) {
                const int mt = slot >> 1;
                const int rh = slot & 1;
                const int row = rowBase + wm * 32 + mt * 16 + rh * 8 + (lane >> 2);

                float dist[32];          // constant-indexed only -> registers
                float mn = __int_as_float(0x7f800000);
#pragma unroll
                for (int j = 0; j < 16; j++) {
#pragma unroll
                    for (int q = 0; q < 2; q++) {
                        float d = fmaf(-2.f, acc[mt][j][rh * 2 + q],
                                       sc2[cbase + j * 8 + q]);
                        dist[j * 2 + q] = d;
                        mn = fminf(mn, d);
                    }
                }
                mn = fminf(mn, __shfl_xor_sync(0xffffffffu, mn, 1));
                mn = fminf(mn, __shfl_xor_sync(0xffffffffu, mn, 2));
                const float thr = mn + MARGIN;

                // candidate scan: fully unrolled; cand[] (local) written rarely
                int cand[32];
                int nc = 0;
#pragma unroll
                for (int u = 0; u < 32; u++) {
                    if (dist[u] < thr)
                        cand[nc++] = cbase + (u >> 1) * 8 + (u & 1);
                }

                const float4* xrow = reinterpret_cast<const float4*>(
                    g_fmap + (long long)row * DMODEL);
                for (int i = 0; i < nc; i++) {
                    const int code = cand[i];
                    const float4* crow = reinterpret_cast<const float4*>(
                        cbk + (long long)code * DMODEL);
                    float s0 = 0.f, s1 = 0.f, s2 = 0.f, s3 = 0.f;
#pragma unroll 8
                    for (int u = 0; u < 64; u++) {
                        float4 av = xrow[u];
                        float4 bv = crow[u];
                        s0 = fmaf(av.x, bv.x, s0);
                        s1 = fmaf(av.y, bv.y, s1);
                        s2 = fmaf(av.z, bv.z, s2);
                        s3 = fmaf(av.w, bv.w, s3);
                    }
                    float de = fmaf(-2.f, (s0 + s1) + (s2 + s3), sc2[code]);
                    if (de < bestE[slot] || (de == bestE[slot] && code < bestC[slot])) {
                        bestE[slot] = de;
                        bestC[slot] = code;
                    }
                }
            }
        }
    }

    // ---- combine: quad lanes -> per-warp; then across the two wn warps ----
#pragma unroll
    for (int slot = 0; slot < 4; slot++) {
        const int mt = slot >> 1;
        const int rh = slot & 1;
        float e = bestE[slot];
        int   c = bestC[slot];
#pragma unroll
        for (int off = 1; off < 4; off <<= 1) {
            float oe = __shfl_xor_sync(0xffffffffu, e, off);
            int   oc = __shfl_xor_sync(0xffffffffu, c, off);
            if (oe < e || (oe == e && oc < c)) { e = oe; c = oc; }
        }
        if ((lane & 3) == 0) {
            const int r = wm * 32 + mt * 16 + rh * 8 + (lane >> 2);
            sE[wn][r] = e;
            sC[wn][r] = c;
        }
    }
    __syncthreads();

    if (tid < 128) {
        float e0 = sE[0][tid], e1 = sE[1][tid];
        int   c0 = sC[0][tid], c1 = sC[1][tid];
        bool take1 = (e1 < e0) || (e1 == e0 && c1 < c0);
        int   c = take1 ? c1 : c0;
        float e = take1 ? e1 : e0;
        s_idx[tid] = c;
        s_red[tid] = e;
        out[QUANT_ELEMS + (long long)blockIdx.x * 128 + tid] = (float)c;
    }
    __syncthreads();

    for (int s = 64; s > 0; s >>= 1) {
        if (tid < s) s_red[tid] += s_red[tid + s];
        __syncthreads();
    }
    if (tid == 0) g_vq_partial[blockIdx.x] = s_red[0];

    // quant NCHW writes
    {
        const int b = blockIdx.x >> 7;
        const int h = blockIdx.x & 127;
        const int w    = tid & 127;
        const int doff = tid >> 7;
        const int myIdx = s_idx[w];
        for (int db = 0; db < DMODEL; db += 2) {
            int d = db + doff;
            float qv = cbk[myIdx * DMODEL + d];
            out[(((long long)(b * DMODEL + d) * 128 + h) << 7) + w] = qv;
        }
    }
}

// =====================================================================
// Kernel 4: final loss
// =====================================================================
__global__ void loss_kernel(float* __restrict__ out)
{
    __shared__ float red[256];
    float s = 0.f;
    for (int i = threadIdx.x; i < 2048; i += 256)
        s += g_conv_partial[i] + g_vq_partial[i];
    red[threadIdx.x] = s;
    __syncthreads();
    for (int st = 128; st > 0; st >>= 1) {
        if (threadIdx.x < st) red[threadIdx.x] += red[threadIdx.x + st];
        __syncthreads();
    }
    if (threadIdx.x == 0)
        out[QUANT_ELEMS + IDX_ELEMS] = red[0] * (1.0f / 67108864.0f);
}

// =====================================================================
extern "C" void kernel_launch(void* const* d_in, const int* in_sizes, int n_in,
                              void* d_out, int out_size)
{
    (void)in_sizes; (void)n_in; (void)out_size;
    const float* x    = (const float*)d_in[0];
    const float* cw   = (const float*)d_in[1];
    const float* cbia = (const float*)d_in[2];
    const float* gam  = (const float*)d_in[3];
    const float* bet  = (const float*)d_in[4];
    const float* mu   = (const float*)d_in[5];
    const float* var  = (const float*)d_in[6];
    const float* cbk  = (const float*)d_in[7];
    float* out = (float*)d_out;

    cudaFuncSetAttribute(vq_kernel, cudaFuncAttributeMaxDynamicSharedMemorySize, VQ_SMEM);

    conv_kernel<<<2048, 256>>>(x, cw, cbia, gam, bet, mu, var);
    prep_cbk_kernel<<<512, 256>>>(cbk);
    vq_kernel<<<2048, 256, VQ_SMEM>>>(cbk, out);
    loss_kernel<<<1, 256>>>(out);
}

// round 6
// speedup vs baseline: 3.6958x; 1.0602x over previous
#include <cuda_runtime.h>
#include <cuda_bf16.h>
#include <cstdint>

// ---------------- problem constants ----------------
#define BATCH   16
#define DMODEL  256
#define KCODES  512
#define HP      128
#define WP      128
#define NROWS   (BATCH*HP*WP)                         // 262144
#define QUANT_ELEMS ((long long)BATCH*DMODEL*HP*WP)   // 67108864
#define IDX_ELEMS   (BATCH*HP*WP)
#define BN_EPS 1e-5f
#define MARGIN 4.0f

// ---------------- scratch ----------------
__device__ __nv_bfloat16  g_cbkb[KCODES * DMODEL];             // bf16 codebook
__device__ float g_c2[KCODES];
__device__ float g_conv_partial[2048];
__device__ float g_vq_partial[2048];

// ---------------- f32x2 helpers (conv) ----------------
__device__ __forceinline__ unsigned long long pack2(float a, float b) {
    unsigned long long r;
    asm("mov.b64 %0, {%1, %2};" : "=l"(r) : "f"(a), "f"(b));
    return r;
}
__device__ __forceinline__ void unpack2(unsigned long long v, float& a, float& b) {
    asm("mov.b64 {%0, %1}, %2;" : "=f"(a), "=f"(b) : "l"(v));
}
__device__ __forceinline__ void fma2(unsigned long long& acc,
                                     unsigned long long a, unsigned long long b) {
    asm("fma.rn.f32x2 %0, %1, %2, %3;" : "=l"(acc) : "l"(a), "l"(b), "l"(acc));
}

// ---------------- smem / cp.async / ldmatrix / mma ----------------
__device__ __forceinline__ uint32_t smem_u32(const void* p) {
    uint32_t a;
    asm("{ .reg .u64 t; cvta.to.shared.u64 t, %1; cvt.u32.u64 %0, t; }" : "=r"(a) : "l"(p));
    return a;
}
__device__ __forceinline__ void cp_async16(uint32_t dst, const void* src) {
    asm volatile("cp.async.cg.shared.global [%0], [%1], 16;" :: "r"(dst), "l"(src) : "memory");
}
#define CP_COMMIT() asm volatile("cp.async.commit_group;" ::: "memory")
#define CP_WAIT(n)  asm volatile("cp.async.wait_group %0;" :: "n"(n) : "memory")

__device__ __forceinline__ void ldm_x4(uint32_t addr, uint32_t& r0, uint32_t& r1,
                                       uint32_t& r2, uint32_t& r3) {
    asm volatile("ldmatrix.sync.aligned.m8n8.x4.shared.b16 {%0,%1,%2,%3}, [%4];"
                 : "=r"(r0), "=r"(r1), "=r"(r2), "=r"(r3) : "r"(addr));
}
__device__ __forceinline__ void mma16816(float* c, const uint32_t* a,
                                         uint32_t b0, uint32_t b1) {
    asm volatile("mma.sync.aligned.m16n8k16.row.col.f32.bf16.bf16.f32 "
                 "{%0,%1,%2,%3}, {%4,%5,%6,%7}, {%8,%9}, {%0,%1,%2,%3};"
                 : "+f"(c[0]), "+f"(c[1]), "+f"(c[2]), "+f"(c[3])
                 : "r"(a[0]), "r"(a[1]), "r"(a[2]), "r"(a[3]), "r"(b0), "r"(b1));
}

// ---------------- smem layout (dynamic) ----------------
#define XSTRIDE  260                    // floats per sXf row (16B aligned, conflict-free)
#define SXF_BYTES (128*XSTRIDE*4)       // 133120
#define ASTRIDE  144
#define ACH_OFF  SXF_BYTES              // A bf16 chunk (128 x 64k), 18432 B
#define ACH_BYTES (128*ASTRIDE)
#define B_OFF    (ACH_OFF + ACH_BYTES)  // 151552
#define BTILE    (256*ASTRIDE)          // 36864
#define FUSED_SMEM (B_OFF + 2*BTILE)    // 225280

// =====================================================================
// Kernel A: codebook -> bf16 + exact fp32 squared norms
// =====================================================================
__global__ __launch_bounds__(256) void prep_cbk_kernel(const float* __restrict__ cbk)
{
    __shared__ float red[256];
    const int k = blockIdx.x;
    const int t = threadIdx.x;
    float v = cbk[k * DMODEL + t];
    g_cbkb[k * DMODEL + t] = __float2bfloat16(v);
    red[t] = v * v;
    __syncthreads();
    for (int s = 128; s > 0; s >>= 1) {
        if (t < s) red[t] += red[t + s];
        __syncthreads();
    }
    if (t == 0) g_c2[k] = red[0];
}

// =====================================================================
// Kernel B: FUSED conv3x3+bias+maxpool+BN+GELU  ->  smem x-tile  ->
//           bf16 MMA VQ + margin-filtered exact fp32 rescore (smem x) ->
//           quant NCHW write + indices + loss partials
// grid 2048 (one (b,ph) tile = 128 rows); 256 threads = 8 warps (4m x 2n)
// =====================================================================
__global__ __launch_bounds__(256, 1) void fused_kernel(
    const float* __restrict__ x, const float* __restrict__ cw,
    const float* __restrict__ cbias,
    const float* __restrict__ gam, const float* __restrict__ bet,
    const float* __restrict__ mu,  const float* __restrict__ var,
    const float* __restrict__ cbk, float* __restrict__ out)
{
    extern __shared__ __align__(16) char dsm[];
    __shared__ float sc2[KCODES];
    __shared__ float red[256];
    __shared__ float sE[2][128];
    __shared__ int   sC[2][128];
    __shared__ int   s_idx[128];
    __shared__ float s_red[128];

    const int tid  = threadIdx.x;
    const int wid  = tid >> 5;
    const int lane = tid & 31;
    const int wm   = wid >> 1;
    const int wn   = wid & 1;
    const int bx   = blockIdx.x;
    const int b    = bx >> 7;
    const int ph   = bx & 127;

    float* sXf = reinterpret_cast<float*>(dsm);
    const uint32_t smBase = smem_u32(dsm);

    sc2[tid]       = g_c2[tid];
    sc2[tid + 256] = g_c2[tid + 256];

    // ================= conv phase =================
    {
        // sIn aliases the B region (B unused until after conv completes)
        float (*sIn)[4][258] = reinterpret_cast<float (*)[4][258]>(dsm + B_OFF);
        const int d  = tid;
        const int h0 = 2 * ph - 1;
        for (int t = tid; t < 3 * 4 * 258; t += 256) {
            int c   = t / 1032;
            int rem = t - c * 1032;
            int i   = rem / 258;
            int j   = rem - i * 258;
            int gr  = h0 + i;
            int gc  = j - 1;
            float v = 0.f;
            if ((unsigned)gr < 256u && (unsigned)gc < 256u)
                v = x[(((b * 3 + c) << 8) + gr) * 256 + gc];
            sIn[c][i][j] = v;
        }

        unsigned long long w2[27];
#pragma unroll
        for (int j = 0; j < 27; j++) { float wv = cw[d * 27 + j]; w2[j] = pack2(wv, wv); }
        const float bias = cbias[d];
        const float inv  = gam[d] * rsqrtf(var[d] + BN_EPS);
        const float shf  = bet[d] - mu[d] * inv;

        __syncthreads();

        float sumsq = 0.f;
        for (int pw = 0; pw < 128; ++pw) {
            unsigned long long acc0 = 0ull, acc1 = 0ull;
#pragma unroll
            for (int c = 0; c < 3; c++) {
                const int wb = c * 9;
#pragma unroll
                for (int ro = 0; ro < 4; ro++) {
                    const float* p = &sIn[c][ro][2 * pw];
                    unsigned long long g01 = *reinterpret_cast<const unsigned long long*>(p);
                    unsigned long long g23 = *reinterpret_cast<const unsigned long long*>(p + 2);
                    float f0, f1, f2, f3;
                    unpack2(g01, f0, f1);
                    unpack2(g23, f2, f3);
                    unsigned long long g12 = pack2(f1, f2);
                    if (ro <= 2) {
                        fma2(acc0, g01, w2[wb + ro * 3 + 0]);
                        fma2(acc0, g12, w2[wb + ro * 3 + 1]);
                        fma2(acc0, g23, w2[wb + ro * 3 + 2]);
                    }
                    if (ro >= 1) {
                        fma2(acc1, g01, w2[wb + (ro - 1) * 3 + 0]);
                        fma2(acc1, g12, w2[wb + (ro - 1) * 3 + 1]);
                        fma2(acc1, g23, w2[wb + (ro - 1) * 3 + 2]);
                    }
                }
            }
            float a0, a1, b0v, b1v;
            unpack2(acc0, a0, a1);
            unpack2(acc1, b0v, b1v);
            float m = fmaxf(fmaxf(a0, a1), fmaxf(b0v, b1v)) + bias;
            float v = m * inv + shf;
            float g = 0.5f * v * (1.0f + erff(v * 0.7071067811865476f));
            sXf[pw * XSTRIDE + d] = g;
            sumsq += g * g;
        }

        red[tid] = sumsq;
        __syncthreads();
        for (int s = 128; s > 0; s >>= 1) {
            if (tid < s) red[tid] += red[tid + s];
            __syncthreads();
        }
        if (tid == 0) g_conv_partial[bx] = red[0];
        __syncthreads();   // sXf complete; sIn region now dead
    }

    // ================= VQ phase =================
    auto issue_B = [&](int p) {
        const int half = p >> 2;
        const int kc   = p & 3;
        const uint32_t buf = smBase + B_OFF + (p & 1) * BTILE;
#pragma unroll
        for (int it = 0; it < 8; it++) {
            int idx = tid + it * 256;
            int c   = idx >> 3;
            int g   = idx & 7;
            const void* src = g_cbkb + ((half * 256 + c) * DMODEL + kc * 64 + g * 8);
            cp_async16(buf + c * ASTRIDE + g * 16, src);
        }
        CP_COMMIT();
    };

    float bestE[4];
    int   bestC[4];
#pragma unroll
    for (int s = 0; s < 4; s++) { bestE[s] = __int_as_float(0x7f800000); bestC[s] = 0; }

    float acc[2][16][4];

    issue_B(0);

    for (int p = 0; p < 8; p++) {
        const int half = p >> 2;
        const int kc   = p & 3;
        const uint32_t bbuf = smBase + B_OFF + (p & 1) * BTILE;

        // ---- convert A chunk kc: sXf fp32 -> bf16 ldmatrix layout ----
        {
            const int r  = tid >> 1;
            const int kg = tid & 1;
            const float* src = sXf + r * XSTRIDE + kc * 64 + kg * 32;
            char* dstA = dsm + ACH_OFF + r * ASTRIDE + kg * 64;
#pragma unroll
            for (int i = 0; i < 8; i++) {
                float4 v = *reinterpret_cast<const float4*>(src + i * 4);
                __nv_bfloat162 h01 = __float22bfloat162_rn(make_float2(v.x, v.y));
                __nv_bfloat162 h23 = __float22bfloat162_rn(make_float2(v.z, v.w));
                uint2 st;
                st.x = *reinterpret_cast<uint32_t*>(&h01);
                st.y = *reinterpret_cast<uint32_t*>(&h23);
                *reinterpret_cast<uint2*>(dstA + i * 8) = st;
            }
        }

        if (p < 7) { issue_B(p + 1); CP_WAIT(1); }
        else       { CP_WAIT(0); }
        __syncthreads();   // A chunk + B tile visible to all

        if (kc == 0) {
#pragma unroll
            for (int mt = 0; mt < 2; mt++)
#pragma unroll
                for (int j = 0; j < 16; j++)
#pragma unroll
                    for (int q = 0; q < 4; q++) acc[mt][j][q] = 0.f;
        }

#pragma unroll
        for (int ks = 0; ks < 4; ks++) {
            uint32_t a[2][4];
#pragma unroll
            for (int mt = 0; mt < 2; mt++) {
                int grp = lane >> 3, rim = lane & 7;
                uint32_t row  = wm * 32 + mt * 16 + (grp & 1) * 8 + rim;
                uint32_t koff = ks * 32 + (grp >> 1) * 16;
                ldm_x4(smBase + ACH_OFF + row * ASTRIDE + koff,
                       a[mt][0], a[mt][1], a[mt][2], a[mt][3]);
            }
#pragma unroll
            for (int jj = 0; jj < 8; jj++) {
                int grp = lane >> 3, rim = lane & 7;
                uint32_t codeInTile = wn * 128 + (2 * jj + (grp >> 1)) * 8 + rim;
                uint32_t addr = bbuf + codeInTile * ASTRIDE + ks * 32 + (grp & 1) * 16;
                uint32_t b0, b1, b2, b3;
                ldm_x4(addr, b0, b1, b2, b3);
#pragma unroll
                for (int mt = 0; mt < 2; mt++) {
                    mma16816(acc[mt][2 * jj],     a[mt], b0, b1);
                    mma16816(acc[mt][2 * jj + 1], a[mt], b2, b3);
                }
            }
        }
        __syncthreads();   // A/B consumed before next conversion/load

        if (kc == 3) {
            // ---- epilogue: approx distances (regs) + exact rescore from smem ----
            const int cbase = half * 256 + wn * 128 + (lane & 3) * 2;
#pragma unroll
            for (int slot = 0; slot < 4; slot++) {
                const int mt = slot >> 1;
                const int rh = slot & 1;
                const int rowLocal = wm * 32 + mt * 16 + rh * 8 + (lane >> 2);

                float dist[32];
                float mn = __int_as_float(0x7f800000);
#pragma unroll
                for (int j = 0; j < 16; j++) {
#pragma unroll
                    for (int q = 0; q < 2; q++) {
                        float d = fmaf(-2.f, acc[mt][j][rh * 2 + q],
                                       sc2[cbase + j * 8 + q]);
                        dist[j * 2 + q] = d;
                        mn = fminf(mn, d);
                    }
                }
                mn = fminf(mn, __shfl_xor_sync(0xffffffffu, mn, 1));
                mn = fminf(mn, __shfl_xor_sync(0xffffffffu, mn, 2));
                const float thr = mn + MARGIN;

                int cand[32];
                int nc = 0;
#pragma unroll
                for (int u = 0; u < 32; u++) {
                    if (dist[u] < thr)
                        cand[nc++] = cbase + (u >> 1) * 8 + (u & 1);
                }

                const float4* xrow = reinterpret_cast<const float4*>(
                    sXf + rowLocal * XSTRIDE);
                for (int i = 0; i < nc; i++) {
                    const int code = cand[i];
                    const float4* crow = reinterpret_cast<const float4*>(
                        cbk + (long long)code * DMODEL);
                    float s0 = 0.f, s1 = 0.f, s2 = 0.f, s3 = 0.f;
#pragma unroll 8
                    for (int u = 0; u < 64; u++) {
                        float4 av = xrow[u];
                        float4 bv = crow[u];
                        s0 = fmaf(av.x, bv.x, s0);
                        s1 = fmaf(av.y, bv.y, s1);
                        s2 = fmaf(av.z, bv.z, s2);
                        s3 = fmaf(av.w, bv.w, s3);
                    }
                    float de = fmaf(-2.f, (s0 + s1) + (s2 + s3), sc2[code]);
                    if (de < bestE[slot] || (de == bestE[slot] && code < bestC[slot])) {
                        bestE[slot] = de;
                        bestC[slot] = code;
                    }
                }
            }
        }
    }

    // ---- combine: quad lanes -> per-warp; then across the two wn warps ----
#pragma unroll
    for (int slot = 0; slot < 4; slot++) {
        const int mt = slot >> 1;
        const int rh = slot & 1;
        float e = bestE[slot];
        int   c = bestC[slot];
#pragma unroll
        for (int off = 1; off < 4; off <<= 1) {
            float oe = __shfl_xor_sync(0xffffffffu, e, off);
            int   oc = __shfl_xor_sync(0xffffffffu, c, off);
            if (oe < e || (oe == e && oc < c)) { e = oe; c = oc; }
        }
        if ((lane & 3) == 0) {
            const int r = wm * 32 + mt * 16 + rh * 8 + (lane >> 2);
            sE[wn][r] = e;
            sC[wn][r] = c;
        }
    }
    __syncthreads();

    if (tid < 128) {
        float e0 = sE[0][tid], e1 = sE[1][tid];
        int   c0 = sC[0][tid], c1 = sC[1][tid];
        bool take1 = (e1 < e0) || (e1 == e0 && c1 < c0);
        int   c = take1 ? c1 : c0;
        float e = take1 ? e1 : e0;
        s_idx[tid] = c;
        s_red[tid] = e;
        out[QUANT_ELEMS + (long long)bx * 128 + tid] = (float)c;
    }
    __syncthreads();

    for (int s = 64; s > 0; s >>= 1) {
        if (tid < s) s_red[tid] += s_red[tid + s];
        __syncthreads();
    }
    if (tid == 0) g_vq_partial[bx] = s_red[0];

    // quant NCHW writes
    {
        const int w    = tid & 127;
        const int doff = tid >> 7;
        const int myIdx = s_idx[w];
        const int h = ph;
        for (int db = 0; db < DMODEL; db += 2) {
            int d = db + doff;
            float qv = cbk[myIdx * DMODEL + d];
            out[(((long long)(b * DMODEL + d) * 128 + h) << 7) + w] = qv;
        }
    }
}

// =====================================================================
// Kernel C: final loss
// =====================================================================
__global__ void loss_kernel(float* __restrict__ out)
{
    __shared__ float red[256];
    float s = 0.f;
    for (int i = threadIdx.x; i < 2048; i += 256)
        s += g_conv_partial[i] + g_vq_partial[i];
    red[threadIdx.x] = s;
    __syncthreads();
    for (int st = 128; st > 0; st >>= 1) {
        if (threadIdx.x < st) red[threadIdx.x] += red[threadIdx.x + st];
        __syncthreads();
    }
    if (threadIdx.x == 0)
        out[QUANT_ELEMS + IDX_ELEMS] = red[0] * (1.0f / 67108864.0f);
}

// =====================================================================
extern "C" void kernel_launch(void* const* d_in, const int* in_sizes, int n_in,
                              void* d_out, int out_size)
{
    (void)in_sizes; (void)n_in; (void)out_size;
    const float* x    = (const float*)d_in[0];
    const float* cw   = (const float*)d_in[1];
    const float* cbia = (const float*)d_in[2];
    const float* gam  = (const float*)d_in[3];
    const float* bet  = (const float*)d_in[4];
    const float* mu   = (const float*)d_in[5];
    const float* var  = (const float*)d_in[6];
    const float* cbk  = (const float*)d_in[7];
    float* out = (float*)d_out;

    cudaFuncSetAttribute(fused_kernel, cudaFuncAttributeMaxDynamicSharedMemorySize,
                         FUSED_SMEM);

    prep_cbk_kernel<<<512, 256>>>(cbk);
    fused_kernel<<<2048, 256, FUSED_SMEM>>>(x, cw, cbia, gam, bet, mu, var, cbk, out);
    loss_kernel<<<1, 256>>>(out);
}